// round 15
// baseline (speedup 1.0000x reference)
#include <cuda_runtime.h>
#include <cuda_bf16.h>
#include <cstdint>

#define BATCH 2048
#define LR 49          // K_REG
#define DIM 2048

// k2 SMEM layout (bytes). V half: 49 rows x 516 b32 (1024 bf16 + 4 b32 pad)
#define VS 516
#define OFF_B   101136                 // B tile (56 x 36 b32) / Wv union (49 x 57 f32)
#define OFF_GK  112336
#define K2_SMEM 113664

// __device__ scratch (allocation-free)
__device__ __nv_bfloat16 wv_bf[LR * DIM];        // bf16 copy of W_v
__device__ float part_scr[16 * BATCH * LR];      // [type*8+ksp][batch][k] partials
__device__ float g_scr[BATCH * LR];              // h_t @ W_g^T (reduced)
__device__ float sent_scr[BATCH];                // sentinel logit

__device__ __forceinline__ uint32_t smem_u32(const void* p) {
    uint32_t a;
    asm("{ .reg .u64 t; cvta.to.shared.u64 t, %1; cvt.u32.u64 %0, t; }" : "=r"(a) : "l"(p));
    return a;
}

// ---------------------------------------------------------------------------
// Kernel 1: split-K MMA GEMM (measured 12.7us). grid 256.
// ---------------------------------------------------------------------------
__global__ __launch_bounds__(256) void k1(
    const float* __restrict__ h_t, const float* __restrict__ s_t,
    const float* __restrict__ W_v, const float* __restrict__ W_g,
    const float* __restrict__ W_s)
{
    __shared__ __align__(16) unsigned char raw[29184];
    __nv_bfloat16* A_sm = (__nv_bfloat16*)raw;            // 128 x 72 bf16
    __nv_bfloat16* B_sm = (__nv_bfloat16*)(raw + 18432);  // 56 x 72 bf16
    unsigned* Au = (unsigned*)A_sm;
    unsigned* Bu = (unsigned*)B_sm;
    float (*P)[57] = (float (*)[57])raw;

    const int tid = threadIdx.x;
    const int warp = tid >> 5, lane = tid & 31;
    const int typ = blockIdx.x >> 7;
    const int btile = (blockIdx.x >> 3) & 15;
    const int ksp = blockIdx.x & 7;
    const int b0 = btile * 128;
    const int kbase = ksp * 256;
    const float* X = typ ? s_t : h_t;
    const float* W = typ ? W_s : W_g;
    float* dst = part_scr + (size_t)(typ * 8 + ksp) * BATCH * LR;

    if (tid < 98) {
        int i = blockIdx.x * 98 + tid;
        float4 v = ((const float4*)W_v)[i];
        __nv_bfloat162 lo = __floats2bfloat162_rn(v.x, v.y);
        __nv_bfloat162 hi = __floats2bfloat162_rn(v.z, v.w);
        __nv_bfloat162* d = (__nv_bfloat162*)(wv_bf) + (size_t)i * 2;
        d[0] = lo; d[1] = hi;
    }

    for (int i = tid; i < 29184 / 4; i += 256) ((unsigned*)raw)[i] = 0u;

    const float* asrc[8]; int adst[8];
    #pragma unroll
    for (int s = 0; s < 8; s++) {
        int a = s * 256 + tid;
        int row = a >> 4, c4 = a & 15;
        asrc[s] = X + (size_t)(b0 + row) * DIM + kbase + c4 * 4;
        adst[s] = row * 72 + c4 * 4;
    }
    const float* bsrc[4]; int bdst[4]; bool bact[4]; bool bzero[4];
    #pragma unroll
    for (int s = 0; s < 4; s++) {
        int idx = s * 256 + tid;
        bact[s] = (idx < 896);
        int row = idx >> 4, c4 = idx & 15;
        bzero[s] = (row >= LR);
        int rowc = (row < LR) ? row : 0;
        bsrc[s] = W + (size_t)rowc * DIM + kbase + c4 * 4;
        bdst[s] = row * 72 + c4 * 4;
    }

    float acc[7][4];
    #pragma unroll
    for (int j = 0; j < 7; j++) { acc[j][0]=acc[j][1]=acc[j][2]=acc[j][3]=0.f; }

    float4 ra[8], rbv[4];
    #pragma unroll
    for (int s = 0; s < 8; s++) ra[s] = *(const float4*)(asrc[s]);
    #pragma unroll
    for (int s = 0; s < 4; s++) if (bact[s]) rbv[s] = *(const float4*)(bsrc[s]);
    __syncthreads();

    #pragma unroll 1
    for (int ch = 0; ch < 4; ch++) {
        #pragma unroll
        for (int s = 0; s < 8; s++) {
            __nv_bfloat162 p0 = __floats2bfloat162_rn(ra[s].x, ra[s].y);
            __nv_bfloat162 p1 = __floats2bfloat162_rn(ra[s].z, ra[s].w);
            __nv_bfloat162* d = (__nv_bfloat162*)(A_sm + adst[s]);
            d[0] = p0; d[1] = p1;
        }
        #pragma unroll
        for (int s = 0; s < 4; s++) {
            if (bact[s]) {
                float4 v = bzero[s] ? make_float4(0.f,0.f,0.f,0.f) : rbv[s];
                __nv_bfloat162 p0 = __floats2bfloat162_rn(v.x, v.y);
                __nv_bfloat162 p1 = __floats2bfloat162_rn(v.z, v.w);
                __nv_bfloat162* d = (__nv_bfloat162*)(B_sm + bdst[s]);
                d[0] = p0; d[1] = p1;
            }
        }
        __syncthreads();
        if (ch + 1 < 4) {
            #pragma unroll
            for (int s = 0; s < 8; s++) ra[s] = *(const float4*)(asrc[s] + (ch + 1) * 64);
            #pragma unroll
            for (int s = 0; s < 4; s++) if (bact[s]) rbv[s] = *(const float4*)(bsrc[s] + (ch + 1) * 64);
        }
        #pragma unroll
        for (int st = 0; st < 4; st++) {
            int baseu = st * 8;
            int ai = (warp * 16 + (lane >> 2)) * 36 + baseu + (lane & 3);
            unsigned a0 = Au[ai];
            unsigned a1 = Au[ai + 8 * 36];
            unsigned a2 = Au[ai + 4];
            unsigned a3 = Au[ai + 8 * 36 + 4];
            #pragma unroll
            for (int j = 0; j < 7; j++) {
                int bidx = (j * 8 + (lane >> 2)) * 36 + baseu + (lane & 3);
                unsigned bb0 = Bu[bidx];
                unsigned bb1 = Bu[bidx + 4];
                asm volatile(
                    "mma.sync.aligned.m16n8k16.row.col.f32.bf16.bf16.f32 "
                    "{%0,%1,%2,%3}, {%4,%5,%6,%7}, {%8,%9}, {%0,%1,%2,%3};\n"
                    : "+f"(acc[j][0]), "+f"(acc[j][1]), "+f"(acc[j][2]), "+f"(acc[j][3])
                    : "r"(a0), "r"(a1), "r"(a2), "r"(a3), "r"(bb0), "r"(bb1));
            }
        }
        __syncthreads();
    }

    #pragma unroll
    for (int j = 0; j < 7; j++) {
        int r = warp * 16 + (lane >> 2);
        int c = j * 8 + 2 * (lane & 3);
        P[r][c]         = acc[j][0];
        P[r][c + 1]     = acc[j][1];
        P[r + 8][c]     = acc[j][2];
        P[r + 8][c + 1] = acc[j][3];
    }
    __syncthreads();
    for (int idx = tid; idx < 128 * LR; idx += 256) {
        int row = idx / LR, k = idx - row * LR;
        dst[(size_t)(b0 + row) * LR + k] = P[row][k];
    }
}

// ---------------------------------------------------------------------------
// Kernel 1b: reduce split-K partials -> g_scr; sent[b] (~3us)
// ---------------------------------------------------------------------------
__global__ __launch_bounds__(256) void k1b(const float* __restrict__ w_h_s)
{
    const int warp = threadIdx.x >> 5, lane = threadIdx.x & 31;
    const int b = blockIdx.x * 8 + warp;
    float s = 0.f;

    if (lane < LR) {
        float g = 0.f, S = 0.f;
        #pragma unroll
        for (int i = 0; i < 8; i++) {
            g += part_scr[((size_t)i * BATCH + b) * LR + lane];
            S += part_scr[((size_t)(8 + i) * BATCH + b) * LR + lane];
        }
        g_scr[(size_t)b * LR + lane] = g;
        s = tanhf(g + S) * w_h_s[lane];
    }
    if (lane + 32 < LR) {
        float g = 0.f, S = 0.f;
        #pragma unroll
        for (int i = 0; i < 8; i++) {
            g += part_scr[((size_t)i * BATCH + b) * LR + lane + 32];
            S += part_scr[((size_t)(8 + i) * BATCH + b) * LR + lane + 32];
        }
        g_scr[(size_t)b * LR + lane + 32] = g;
        s += tanhf(g + S) * w_h_s[lane + 32];
    }
    #pragma unroll
    for (int o = 16; o > 0; o >>= 1) s += __shfl_xor_sync(0xffffffffu, s, o);
    if (lane == 0) sent_scr[b] = s;
}

// ---------------------------------------------------------------------------
// Kernel 2: 2-CTA cluster per batch. Each CTA holds its D-half of V in SMEM
// (bf16, read from DRAM ONCE). ~111KB smem/CTA -> 2 CTAs/SM (16 warps).
// Partial WvV per CTA; cross-CTA reduce via DSMEM in the z-loop; softmax
// duplicated; c_t for own half from SMEM. grid 4096, cluster (2,1,1).
// ---------------------------------------------------------------------------
__global__ __launch_bounds__(256) __cluster_dims__(2, 1, 1) void k2(
    const float* __restrict__ V, const float* __restrict__ h_t,
    const float* __restrict__ s_t, const float* __restrict__ w_h,
    float* __restrict__ out)
{
    extern __shared__ __align__(16) unsigned char smraw[];

    const int tid = threadIdx.x;
    const int warp = tid >> 5, lane = tid & 31;
    const int wm = warp & 3;          // m-strip
    const int wn = warp >> 2;         // n-half
    const int b = blockIdx.x >> 1;

    uint32_t rank;
    asm("mov.u32 %0, %%cluster_ctarank;" : "=r"(rank));

    unsigned* Vu = (unsigned*)smraw;                          // 49 x VS b32 (bf16 V half)
    unsigned* Bu = (unsigned*)(smraw + OFF_B);                // 56 x 36 b32 (mainloop)
    __nv_bfloat16* B_sm = (__nv_bfloat16*)(smraw + OFF_B);
    float (*Wv)[57] = (float (*)[57])(smraw + OFF_B);         // 49 x 57 f32 (after mainloop)
    float* gk      = (float*)(smraw + OFF_GK);         // [64]
    float* wh      = (float*)(smraw + OFF_GK + 256);   // [64]
    float* zsm     = (float*)(smraw + OFF_GK + 512);   // [64]
    float* alpha_s = (float*)(smraw + OFF_GK + 768);   // [64]
    float* bet     = (float*)(smraw + OFF_GK + 1024);  // [1]

    // zero B/Wv union (pad rows 49..55 must stay 0 for MMA)
    for (int i = tid; i < 2800; i += 256) Bu[i] = 0u;

    const float* Vb = V + (size_t)b * LR * DIM + rank * 1024;   // own D-half

    // A staging: per chunk 784 float4 (49 rows x 16), 4 slots/thread
    unsigned asrc[4]; int adst[4]; bool aact[4];
    #pragma unroll
    for (int s = 0; s < 4; s++) {
        int a = s * 256 + tid;
        aact[s] = (a < 784);
        int row = aact[s] ? (a >> 4) : 0;
        int c4  = aact[s] ? (a & 15) : 0;
        asrc[s] = (unsigned)(row * DIM + c4 * 4);    // float offset from Vb
        adst[s] = row * VS + c4 * 2;                 // b32 offset in V_sm
    }
    // B staging: per chunk 392 uint4 (49 rows x 8 bf16x8), 2 slots/thread
    unsigned bsrc[2]; int bdst[2]; bool bact[2];
    #pragma unroll
    for (int s = 0; s < 2; s++) {
        int idx = s * 256 + tid;
        bact[s] = (idx < 392);
        int row = bact[s] ? (idx >> 3) : 0;
        int q   = bact[s] ? (idx & 7) : 0;
        bsrc[s] = (unsigned)(row * DIM + rank * 1024 + q * 8);  // bf16 offset in wv_bf
        bdst[s] = row * 72 + q * 8;                             // bf16 offset in B_sm
    }

    // A-fragment rows (clamp >=49 to 48; duplicates discarded in epilogue)
    int ar0 = wm * 16 + (lane >> 2); if (ar0 > 48) ar0 = 48;
    int ar1 = ar0 + 8;               if (ar1 > 48) ar1 = 48;
    const int a0base = ar0 * VS + (lane & 3);
    const int a1base = ar1 * VS + (lane & 3);

    float acc[4][4];
    #pragma unroll
    for (int j = 0; j < 4; j++) { acc[j][0]=acc[j][1]=acc[j][2]=acc[j][3]=0.f; }

    // 2-deep register pipeline over 16 chunks of 64 floats
    float4 ra0[4], ra1[4]; uint4 rb0[2], rb1[2];
    #pragma unroll
    for (int s = 0; s < 4; s++) if (aact[s]) ra0[s] = *(const float4*)(Vb + asrc[s]);
    #pragma unroll
    for (int s = 0; s < 2; s++) if (bact[s]) rb0[s] = *(const uint4*)(wv_bf + bsrc[s]);
    #pragma unroll
    for (int s = 0; s < 4; s++) if (aact[s]) ra1[s] = *(const float4*)(Vb + asrc[s] + 64);
    #pragma unroll
    for (int s = 0; s < 2; s++) if (bact[s]) rb1[s] = *(const uint4*)(wv_bf + bsrc[s] + 64);

    __syncthreads();   // zero-fill complete

    auto step = [&](int ch, float4 (&raS)[4], uint4 (&rbS)[2]) {
        const int chb = ch * 32;   // b32 column base in V_sm
        #pragma unroll
        for (int s = 0; s < 4; s++) {
            if (aact[s]) {
                __nv_bfloat162 p0 = __floats2bfloat162_rn(raS[s].x, raS[s].y);
                __nv_bfloat162 p1 = __floats2bfloat162_rn(raS[s].z, raS[s].w);
                unsigned* d = Vu + adst[s] + chb;
                d[0] = *(unsigned*)&p0; d[1] = *(unsigned*)&p1;
            }
        }
        #pragma unroll
        for (int s = 0; s < 2; s++)
            if (bact[s]) *(uint4*)(B_sm + bdst[s]) = rbS[s];
        __syncthreads();

        if (ch + 2 < 16) {
            #pragma unroll
            for (int s = 0; s < 4; s++)
                if (aact[s]) raS[s] = *(const float4*)(Vb + asrc[s] + (ch + 2) * 64);
            #pragma unroll
            for (int s = 0; s < 2; s++)
                if (bact[s]) rbS[s] = *(const uint4*)(wv_bf + bsrc[s] + (ch + 2) * 64);
        }

        #pragma unroll
        for (int st = 0; st < 4; st++) {
            int baseu = st * 8;
            unsigned a0 = Vu[a0base + chb + baseu];
            unsigned a1 = Vu[a1base + chb + baseu];
            unsigned a2 = Vu[a0base + chb + baseu + 4];
            unsigned a3 = Vu[a1base + chb + baseu + 4];
            #pragma unroll
            for (int j = 0; j < 4; j++) {
                if (wn == 1 && j == 3) continue;   // N=56: cols 0..55
                int bidx = (wn * 32 + j * 8 + (lane >> 2)) * 36 + baseu + (lane & 3);
                unsigned bb0 = Bu[bidx];
                unsigned bb1 = Bu[bidx + 4];
                asm volatile(
                    "mma.sync.aligned.m16n8k16.row.col.f32.bf16.bf16.f32 "
                    "{%0,%1,%2,%3}, {%4,%5,%6,%7}, {%8,%9}, {%0,%1,%2,%3};\n"
                    : "+f"(acc[j][0]), "+f"(acc[j][1]), "+f"(acc[j][2]), "+f"(acc[j][3])
                    : "r"(a0), "r"(a1), "r"(a2), "r"(a3), "r"(bb0), "r"(bb1));
            }
        }
        __syncthreads();
    };

    #pragma unroll 1
    for (int ch = 0; ch < 16; ch += 2) {
        step(ch,     ra0, rb0);
        step(ch + 1, ra1, rb1);
    }

    // ---- partial Wv -> SMEM (rows < 49 only; B no longer read) ----
    {
        int r = wm * 16 + (lane >> 2);
        #pragma unroll
        for (int j = 0; j < 4; j++) {
            if (wn == 1 && j == 3) continue;
            int c = wn * 32 + j * 8 + 2 * (lane & 3);
            if (r < LR) {
                Wv[r][c]     = acc[j][0];
                Wv[r][c + 1] = acc[j][1];
            }
            if (r + 8 < LR) {
                Wv[r + 8][c]     = acc[j][2];
                Wv[r + 8][c + 1] = acc[j][3];
            }
        }
    }
    if (tid < LR) {
        gk[tid] = g_scr[(size_t)b * LR + tid];
        wh[tid] = w_h[tid];
    }
    __syncthreads();

    // cluster barrier: peer's partial Wv must be complete before we read it
    asm volatile("barrier.cluster.arrive.aligned;" ::: "memory");
    asm volatile("barrier.cluster.wait.aligned;" ::: "memory");

    // peer Wv base address (DSMEM)
    uint32_t wv_local = smem_u32(&Wv[0][0]);
    uint32_t wv_peer;
    {
        uint32_t prank = rank ^ 1u;
        asm("mapa.shared::cluster.u32 %0, %1, %2;" : "=r"(wv_peer) : "r"(wv_local), "r"(prank));
    }

    // z[l] = sum_k tanh(own[l,k] + peer[l,k] + g[k]) * w_h[k]; all 256 threads
    {
        int row = tid >> 2; if (row >= LR) row = LR - 1;
        int q = tid & 3;
        float z = 0.f;
        #pragma unroll
        for (int kk = 0; kk < 13; kk++) {
            int k = q + kk * 4;
            if (k < LR) {
                float own = Wv[row][k];
                float pv;
                asm volatile("ld.shared::cluster.f32 %0, [%1];"
                             : "=f"(pv) : "r"(wv_peer + (unsigned)((row * 57 + k) * 4)));
                z += tanhf(own + pv + gk[k]) * wh[k];
            }
        }
        z += __shfl_xor_sync(0xffffffffu, z, 1);
        z += __shfl_xor_sync(0xffffffffu, z, 2);
        if (q == 0) zsm[row] = z;
    }
    __syncthreads();

    // softmax over 50 logits in warp 0 (both CTAs duplicate)
    if (warp == 0) {
        float v0 = (lane < LR) ? zsm[lane] : -1e30f;
        float v1 = -1e30f;
        if (lane + 32 < LR)       v1 = zsm[lane + 32];
        else if (lane + 32 == LR) v1 = sent_scr[b];
        float m = fmaxf(v0, v1);
        #pragma unroll
        for (int o = 16; o > 0; o >>= 1) m = fmaxf(m, __shfl_xor_sync(0xffffffffu, m, o));
        float e0 = __expf(v0 - m), e1 = __expf(v1 - m);
        float s = e0 + e1;
        #pragma unroll
        for (int o = 16; o > 0; o >>= 1) s += __shfl_xor_sync(0xffffffffu, s, o);
        float inv = 1.f / s;
        if (lane < LR)       alpha_s[lane]      = e0 * inv;
        if (lane + 32 < LR)  alpha_s[lane + 32] = e1 * inv;
        if (lane == 17)      bet[0] = e1 * inv;   // logit index 49
    }
    __syncthreads();

    // pass 2: c_t for own D-half from SMEM-resident bf16 V (LDS only)
    {
        float c[4];
        c[0] = c[1] = c[2] = c[3] = 0.f;
        const int cb = tid * 2;   // b32 col base (0..510)
        #pragma unroll 7
        for (int l = 0; l < LR; l++) {
            float a = alpha_s[l];
            uint2 v = *(const uint2*)(Vu + l * VS + cb);
            float2 p0 = __bfloat1622float2(*(__nv_bfloat162*)&v.x);
            float2 p1 = __bfloat1622float2(*(__nv_bfloat162*)&v.y);
            c[0] += a * p0.x; c[1] += a * p0.y;
            c[2] += a * p1.x; c[3] += a * p1.y;
        }
        float be = bet[0];
        float om = 1.f - be;
        size_t base = (size_t)b * DIM + rank * 1024 + tid * 4;
        float4 s4 = *(const float4*)(s_t + base);
        float4 h4 = *(const float4*)(h_t + base);
        float4 o;
        o.x = be * s4.x + om * c[0] + h4.x;
        o.y = be * s4.y + om * c[1] + h4.y;
        o.z = be * s4.z + om * c[2] + h4.z;
        o.w = be * s4.w + om * c[3] + h4.w;
        *(float4*)(out + base) = o;
    }

    // final cluster barrier: peer may still be reading our Wv in its z-loop
    asm volatile("barrier.cluster.arrive.aligned;" ::: "memory");
    asm volatile("barrier.cluster.wait.aligned;" ::: "memory");
}

extern "C" void kernel_launch(void* const* d_in, const int* in_sizes, int n_in,
                              void* d_out, int out_size) {
    const float* V     = (const float*)d_in[0];
    const float* h_t   = (const float*)d_in[1];
    const float* s_t   = (const float*)d_in[2];
    const float* W_v   = (const float*)d_in[3];
    const float* W_g   = (const float*)d_in[4];
    const float* W_s   = (const float*)d_in[5];
    const float* w_h   = (const float*)d_in[6];
    const float* w_h_s = (const float*)d_in[7];
    float* out = (float*)d_out;

    cudaFuncSetAttribute(k2, cudaFuncAttributeMaxDynamicSharedMemorySize, K2_SMEM);

    k1<<<256, 256>>>(h_t, s_t, W_v, W_g, W_s);
    k1b<<<256, 256>>>(w_h_s);
    k2<<<4096, 256, K2_SMEM>>>(V, h_t, s_t, w_h, out);
}

// round 16
// speedup vs baseline: 1.2383x; 1.2383x over previous
#include <cuda_runtime.h>
#include <cuda_bf16.h>
#include <cstdint>

#define BATCH 2048
#define LR 49          // K_REG
#define DIM 2048

// k2 dynamic SMEM layout (bytes): two A/B buffers then scalars
#define BUFSTRIDE 27648            // A (128x72 bf16 = 18432) + B (64x72 bf16 = 9216)
#define OFF_GK    55296
#define K2_SMEM   57120

// __device__ scratch (allocation-free)
__device__ __nv_bfloat16 wv_bf[LR * DIM];        // bf16 copy of W_v
__device__ float part_scr[16 * BATCH * LR];      // [type*8+ksp][batch][k] partials
__device__ float g_scr[BATCH * LR];              // h_t @ W_g^T (reduced)
__device__ float sent_scr[BATCH];                // sentinel logit

// ---------------------------------------------------------------------------
// Kernel 1: split-K MMA GEMM (measured 12.7us). grid 256.
// ---------------------------------------------------------------------------
__global__ __launch_bounds__(256) void k1(
    const float* __restrict__ h_t, const float* __restrict__ s_t,
    const float* __restrict__ W_v, const float* __restrict__ W_g,
    const float* __restrict__ W_s)
{
    __shared__ __align__(16) unsigned char raw[29184];
    __nv_bfloat16* A_sm = (__nv_bfloat16*)raw;            // 128 x 72 bf16
    __nv_bfloat16* B_sm = (__nv_bfloat16*)(raw + 18432);  // 56 x 72 bf16
    unsigned* Au = (unsigned*)A_sm;
    unsigned* Bu = (unsigned*)B_sm;
    float (*P)[57] = (float (*)[57])raw;

    const int tid = threadIdx.x;
    const int warp = tid >> 5, lane = tid & 31;
    const int typ = blockIdx.x >> 7;
    const int btile = (blockIdx.x >> 3) & 15;
    const int ksp = blockIdx.x & 7;
    const int b0 = btile * 128;
    const int kbase = ksp * 256;
    const float* X = typ ? s_t : h_t;
    const float* W = typ ? W_s : W_g;
    float* dst = part_scr + (size_t)(typ * 8 + ksp) * BATCH * LR;

    if (tid < 98) {
        int i = blockIdx.x * 98 + tid;
        float4 v = ((const float4*)W_v)[i];
        __nv_bfloat162 lo = __floats2bfloat162_rn(v.x, v.y);
        __nv_bfloat162 hi = __floats2bfloat162_rn(v.z, v.w);
        __nv_bfloat162* d = (__nv_bfloat162*)(wv_bf) + (size_t)i * 2;
        d[0] = lo; d[1] = hi;
    }

    for (int i = tid; i < 29184 / 4; i += 256) ((unsigned*)raw)[i] = 0u;

    const float* asrc[8]; int adst[8];
    #pragma unroll
    for (int s = 0; s < 8; s++) {
        int a = s * 256 + tid;
        int row = a >> 4, c4 = a & 15;
        asrc[s] = X + (size_t)(b0 + row) * DIM + kbase + c4 * 4;
        adst[s] = row * 72 + c4 * 4;
    }
    const float* bsrc[4]; int bdst[4]; bool bact[4]; bool bzero[4];
    #pragma unroll
    for (int s = 0; s < 4; s++) {
        int idx = s * 256 + tid;
        bact[s] = (idx < 896);
        int row = idx >> 4, c4 = idx & 15;
        bzero[s] = (row >= LR);
        int rowc = (row < LR) ? row : 0;
        bsrc[s] = W + (size_t)rowc * DIM + kbase + c4 * 4;
        bdst[s] = row * 72 + c4 * 4;
    }

    float acc[7][4];
    #pragma unroll
    for (int j = 0; j < 7; j++) { acc[j][0]=acc[j][1]=acc[j][2]=acc[j][3]=0.f; }

    float4 ra[8], rbv[4];
    #pragma unroll
    for (int s = 0; s < 8; s++) ra[s] = *(const float4*)(asrc[s]);
    #pragma unroll
    for (int s = 0; s < 4; s++) if (bact[s]) rbv[s] = *(const float4*)(bsrc[s]);
    __syncthreads();

    #pragma unroll 1
    for (int ch = 0; ch < 4; ch++) {
        #pragma unroll
        for (int s = 0; s < 8; s++) {
            __nv_bfloat162 p0 = __floats2bfloat162_rn(ra[s].x, ra[s].y);
            __nv_bfloat162 p1 = __floats2bfloat162_rn(ra[s].z, ra[s].w);
            __nv_bfloat162* d = (__nv_bfloat162*)(A_sm + adst[s]);
            d[0] = p0; d[1] = p1;
        }
        #pragma unroll
        for (int s = 0; s < 4; s++) {
            if (bact[s]) {
                float4 v = bzero[s] ? make_float4(0.f,0.f,0.f,0.f) : rbv[s];
                __nv_bfloat162 p0 = __floats2bfloat162_rn(v.x, v.y);
                __nv_bfloat162 p1 = __floats2bfloat162_rn(v.z, v.w);
                __nv_bfloat162* d = (__nv_bfloat162*)(B_sm + bdst[s]);
                d[0] = p0; d[1] = p1;
            }
        }
        __syncthreads();
        if (ch + 1 < 4) {
            #pragma unroll
            for (int s = 0; s < 8; s++) ra[s] = *(const float4*)(asrc[s] + (ch + 1) * 64);
            #pragma unroll
            for (int s = 0; s < 4; s++) if (bact[s]) rbv[s] = *(const float4*)(bsrc[s] + (ch + 1) * 64);
        }
        #pragma unroll
        for (int st = 0; st < 4; st++) {
            int baseu = st * 8;
            int ai = (warp * 16 + (lane >> 2)) * 36 + baseu + (lane & 3);
            unsigned a0 = Au[ai];
            unsigned a1 = Au[ai + 8 * 36];
            unsigned a2 = Au[ai + 4];
            unsigned a3 = Au[ai + 8 * 36 + 4];
            #pragma unroll
            for (int j = 0; j < 7; j++) {
                int bidx = (j * 8 + (lane >> 2)) * 36 + baseu + (lane & 3);
                unsigned bb0 = Bu[bidx];
                unsigned bb1 = Bu[bidx + 4];
                asm volatile(
                    "mma.sync.aligned.m16n8k16.row.col.f32.bf16.bf16.f32 "
                    "{%0,%1,%2,%3}, {%4,%5,%6,%7}, {%8,%9}, {%0,%1,%2,%3};\n"
                    : "+f"(acc[j][0]), "+f"(acc[j][1]), "+f"(acc[j][2]), "+f"(acc[j][3])
                    : "r"(a0), "r"(a1), "r"(a2), "r"(a3), "r"(bb0), "r"(bb1));
            }
        }
        __syncthreads();
    }

    #pragma unroll
    for (int j = 0; j < 7; j++) {
        int r = warp * 16 + (lane >> 2);
        int c = j * 8 + 2 * (lane & 3);
        P[r][c]         = acc[j][0];
        P[r][c + 1]     = acc[j][1];
        P[r + 8][c]     = acc[j][2];
        P[r + 8][c + 1] = acc[j][3];
    }
    __syncthreads();
    for (int idx = tid; idx < 128 * LR; idx += 256) {
        int row = idx / LR, k = idx - row * LR;
        dst[(size_t)(b0 + row) * LR + k] = P[row][k];
    }
}

// ---------------------------------------------------------------------------
// Kernel 1b: reduce split-K partials -> g_scr; sent[b] (~3us)
// ---------------------------------------------------------------------------
__global__ __launch_bounds__(256) void k1b(const float* __restrict__ w_h_s)
{
    const int warp = threadIdx.x >> 5, lane = threadIdx.x & 31;
    const int b = blockIdx.x * 8 + warp;
    float s = 0.f;

    if (lane < LR) {
        float g = 0.f, S = 0.f;
        #pragma unroll
        for (int i = 0; i < 8; i++) {
            g += part_scr[((size_t)i * BATCH + b) * LR + lane];
            S += part_scr[((size_t)(8 + i) * BATCH + b) * LR + lane];
        }
        g_scr[(size_t)b * LR + lane] = g;
        s = tanhf(g + S) * w_h_s[lane];
    }
    if (lane + 32 < LR) {
        float g = 0.f, S = 0.f;
        #pragma unroll
        for (int i = 0; i < 8; i++) {
            g += part_scr[((size_t)i * BATCH + b) * LR + lane + 32];
            S += part_scr[((size_t)(8 + i) * BATCH + b) * LR + lane + 32];
        }
        g_scr[(size_t)b * LR + lane + 32] = g;
        s += tanhf(g + S) * w_h_s[lane + 32];
    }
    #pragma unroll
    for (int o = 16; o > 0; o >>= 1) s += __shfl_xor_sync(0xffffffffu, s, o);
    if (lane == 0) sent_scr[b] = s;
}

// ---------------------------------------------------------------------------
// Kernel 2: R12's k2 with DOUBLE-BUFFERED A/B tiles -> 1 barrier per chunk
// instead of 2. Staging regs / MMA / epilogue identical to R12 (264us).
// grid 1024 (2 batches/CTA), block 256, ~57KB dyn smem -> 2 CTAs/SM.
// ---------------------------------------------------------------------------
__global__ __launch_bounds__(256) void k2(
    const float* __restrict__ V, const float* __restrict__ h_t,
    const float* __restrict__ s_t, const float* __restrict__ w_h,
    float* __restrict__ out)
{
    extern __shared__ __align__(16) unsigned char smraw[];

    const int tid = threadIdx.x;
    const int warp = tid >> 5, lane = tid & 31;
    const int b0 = blockIdx.x * 2, b1 = b0 + 1;

    // buffers: A at +0, B at +18432 within each BUFSTRIDE region
    float (*Wv)[65] = (float (*)[65])smraw;     // aliases buffers after GEMM
    float* gk      = (float*)(smraw + OFF_GK);          // [128]
    float* wh      = (float*)(smraw + OFF_GK + 512);    // [64]
    float* zsm     = (float*)(smraw + OFF_GK + 768);    // [128]
    float* alpha_s = (float*)(smraw + OFF_GK + 1280);   // [128]
    float* bet     = (float*)(smraw + OFF_GK + 1792);   // [2]

    // zero both buffers (pad rows/cols stay 0 forever)
    for (int i = tid; i < (2 * BUFSTRIDE) / 4; i += 256) ((unsigned*)smraw)[i] = 0u;

    const float* Vb0 = V + (size_t)b0 * LR * DIM;
    const float* Vb1 = V + (size_t)b1 * LR * DIM;

    // per-thread prefetch slot descriptors (R12 layout, dest as byte offsets)
    const float* asrc[7]; int adst[7]; bool aact[7];
    #pragma unroll
    for (int s = 0; s < 7; s++) {
        int a = s * 256 + tid;
        aact[s] = (a < 1568);
        int batch = (a >= 784) ? 1 : 0;
        int idx = a - 784 * batch;
        int row = idx >> 4, c4 = idx & 15;
        if (!aact[s]) { row = 0; c4 = 0; }
        asrc[s] = (batch ? Vb1 : Vb0) + (size_t)row * DIM + c4 * 4;
        adst[s] = ((batch * 64 + row) * 72 + c4 * 4) * 2;   // byte offset in A region
    }
    const __nv_bfloat16* bsrc[2]; int bdst[2]; bool bact[2];
    #pragma unroll
    for (int s = 0; s < 2; s++) {
        int bidx = s * 256 + tid;
        bact[s] = (bidx < 392);
        int row = bidx >> 3, q = bidx & 7;
        if (!bact[s]) { row = 0; q = 0; }
        bsrc[s] = wv_bf + (size_t)row * DIM + q * 8;
        bdst[s] = 18432 + (row * 72 + q * 8) * 2;           // byte offset in B region
    }

    float acc[8][4];
    #pragma unroll
    for (int j = 0; j < 8; j++) {
        #pragma unroll
        for (int c = 0; c < 4; c++) acc[j][c] = 0.f;
    }

    float4 ra[7]; uint4 rb[2];
    // prefetch chunk 0
    #pragma unroll
    for (int s = 0; s < 7; s++) if (aact[s]) ra[s] = *(const float4*)(asrc[s]);
    #pragma unroll
    for (int s = 0; s < 2; s++) if (bact[s]) rb[s] = *(const uint4*)(bsrc[s]);

    __syncthreads();   // zero-fill complete

    // store chunk 0 -> buffer 0, prefetch chunk 1
    #pragma unroll
    for (int s = 0; s < 7; s++) {
        if (aact[s]) {
            __nv_bfloat162 p0 = __floats2bfloat162_rn(ra[s].x, ra[s].y);
            __nv_bfloat162 p1 = __floats2bfloat162_rn(ra[s].z, ra[s].w);
            __nv_bfloat162* d = (__nv_bfloat162*)(smraw + adst[s]);
            d[0] = p0; d[1] = p1;
        }
    }
    #pragma unroll
    for (int s = 0; s < 2; s++)
        if (bact[s]) *(uint4*)(smraw + bdst[s]) = rb[s];
    #pragma unroll
    for (int s = 0; s < 7; s++) if (aact[s]) ra[s] = *(const float4*)(asrc[s] + 64);
    #pragma unroll
    for (int s = 0; s < 2; s++) if (bact[s]) rb[s] = *(const uint4*)(bsrc[s] + 64);
    __syncthreads();   // buffer 0 ready

    #pragma unroll 1
    for (int ch = 0; ch < 32; ch++) {            // D chunks of 64
        const int cur = (ch & 1) * BUFSTRIDE;
        const int nxt = ((ch + 1) & 1) * BUFSTRIDE;
        const unsigned* Au = (const unsigned*)(smraw + cur);
        const unsigned* Bu = (const unsigned*)(smraw + cur + 18432);

        // store already-fetched chunk ch+1 regs into the other buffer
        if (ch + 1 < 32) {
            #pragma unroll
            for (int s = 0; s < 7; s++) {
                if (aact[s]) {
                    __nv_bfloat162 p0 = __floats2bfloat162_rn(ra[s].x, ra[s].y);
                    __nv_bfloat162 p1 = __floats2bfloat162_rn(ra[s].z, ra[s].w);
                    __nv_bfloat162* d = (__nv_bfloat162*)(smraw + nxt + adst[s]);
                    d[0] = p0; d[1] = p1;
                }
            }
            #pragma unroll
            for (int s = 0; s < 2; s++)
                if (bact[s]) *(uint4*)(smraw + nxt + bdst[s]) = rb[s];
        }
        // issue chunk ch+2 global loads
        if (ch + 2 < 32) {
            #pragma unroll
            for (int s = 0; s < 7; s++)
                if (aact[s]) ra[s] = *(const float4*)(asrc[s] + (ch + 2) * 64);
            #pragma unroll
            for (int s = 0; s < 2; s++)
                if (bact[s]) rb[s] = *(const uint4*)(bsrc[s] + (ch + 2) * 64);
        }

        // MMAs on current buffer
        #pragma unroll
        for (int st = 0; st < 4; st++) {
            int baseu = st * 8;
            int arow = warp * 16 + (lane >> 2);
            int ai = arow * 36 + baseu + (lane & 3);
            unsigned a0 = Au[ai];
            unsigned a1 = Au[ai + 8 * 36];
            unsigned a2 = Au[ai + 4];
            unsigned a3 = Au[ai + 8 * 36 + 4];
            #pragma unroll
            for (int j = 0; j < 8; j++) {
                int bidx = (j * 8 + (lane >> 2)) * 36 + baseu + (lane & 3);
                unsigned bb0 = Bu[bidx];
                unsigned bb1 = Bu[bidx + 4];
                asm volatile(
                    "mma.sync.aligned.m16n8k16.row.col.f32.bf16.bf16.f32 "
                    "{%0,%1,%2,%3}, {%4,%5,%6,%7}, {%8,%9}, {%0,%1,%2,%3};\n"
                    : "+f"(acc[j][0]), "+f"(acc[j][1]), "+f"(acc[j][2]), "+f"(acc[j][3])
                    : "r"(a0), "r"(a1), "r"(a2), "r"(a3), "r"(bb0), "r"(bb1));
            }
        }
        // single barrier: next buffer's stores done + this buffer's reads done
        __syncthreads();
    }

    // ---- epilogue: dump accumulators into aliased SMEM ----
    #pragma unroll
    for (int j = 0; j < 8; j++) {
        int r = warp * 16 + (lane >> 2);
        int c = j * 8 + 2 * (lane & 3);
        Wv[r][c]         = acc[j][0];
        Wv[r][c + 1]     = acc[j][1];
        Wv[r + 8][c]     = acc[j][2];
        Wv[r + 8][c + 1] = acc[j][3];
    }
    if (tid < LR) {
        gk[tid]      = g_scr[(size_t)b0 * LR + tid];
        gk[64 + tid] = g_scr[(size_t)b1 * LR + tid];
        wh[tid]      = w_h[tid];
    }
    __syncthreads();

    // z_t[l] = sum_k tanh(WvV[l,k] + g[k]) * w_h[k]
    {
        int lv = tid >> 1, q = tid & 1;    // lv 0..127
        int gb = lv & 64;
        float z = 0.f;
        for (int k = q; k < LR; k += 2)
            z += tanhf(Wv[lv][k] + gk[gb + k]) * wh[k];
        z += __shfl_xor_sync(0xffffffffu, z, 1);
        if (q == 0) zsm[lv] = z;
    }
    __syncthreads();

    // softmax over 50 logits, warps 0/1 (one per batch)
    if (warp < 2) {
        float v0 = (lane < LR) ? zsm[warp * 64 + lane] : -1e30f;
        float v1 = -1e30f;
        if (lane + 32 < LR)       v1 = zsm[warp * 64 + lane + 32];
        else if (lane + 32 == LR) v1 = sent_scr[b0 + warp];
        float m = fmaxf(v0, v1);
        #pragma unroll
        for (int o = 16; o > 0; o >>= 1) m = fmaxf(m, __shfl_xor_sync(0xffffffffu, m, o));
        float e0 = __expf(v0 - m), e1 = __expf(v1 - m);
        float s = e0 + e1;
        #pragma unroll
        for (int o = 16; o > 0; o >>= 1) s += __shfl_xor_sync(0xffffffffu, s, o);
        float inv = 1.f / s;
        if (lane < LR)       alpha_s[warp * 64 + lane]      = e0 * inv;
        if (lane + 32 < LR)  alpha_s[warp * 64 + lane + 32] = e1 * inv;
        if (lane == 17)      bet[warp] = e1 * inv;   // logit index 49
    }
    __syncthreads();

    // pass 2: c_t + output. Both d-halves of a batch fused -> 14 loads/unroll
    #pragma unroll 1
    for (int pbv = 0; pbv < 2; pbv++) {
        const float* Vb = pbv ? Vb1 : Vb0;
        const float* ap = alpha_s + pbv * 64;
        float c0x = 0.f, c0y = 0.f, c0z = 0.f, c0w = 0.f;
        float c1x = 0.f, c1y = 0.f, c1z = 0.f, c1w = 0.f;
        #pragma unroll 7
        for (int l = 0; l < LR; l++) {
            float a = ap[l];
            float4 v0 = *(const float4*)(Vb + (size_t)l * DIM + tid * 4);
            float4 v1 = *(const float4*)(Vb + (size_t)l * DIM + 1024 + tid * 4);
            c0x += a * v0.x; c0y += a * v0.y; c0z += a * v0.z; c0w += a * v0.w;
            c1x += a * v1.x; c1y += a * v1.y; c1z += a * v1.z; c1w += a * v1.w;
        }
        int b = pbv ? b1 : b0;
        float be = bet[pbv];
        float om = 1.f - be;
        {
            float4 s4 = *(const float4*)(s_t + (size_t)b * DIM + tid * 4);
            float4 h4 = *(const float4*)(h_t + (size_t)b * DIM + tid * 4);
            float4 o;
            o.x = be * s4.x + om * c0x + h4.x;
            o.y = be * s4.y + om * c0y + h4.y;
            o.z = be * s4.z + om * c0z + h4.z;
            o.w = be * s4.w + om * c0w + h4.w;
            *(float4*)(out + (size_t)b * DIM + tid * 4) = o;
        }
        {
            float4 s4 = *(const float4*)(s_t + (size_t)b * DIM + 1024 + tid * 4);
            float4 h4 = *(const float4*)(h_t + (size_t)b * DIM + 1024 + tid * 4);
            float4 o;
            o.x = be * s4.x + om * c1x + h4.x;
            o.y = be * s4.y + om * c1y + h4.y;
            o.z = be * s4.z + om * c1z + h4.z;
            o.w = be * s4.w + om * c1w + h4.w;
            *(float4*)(out + (size_t)b * DIM + 1024 + tid * 4) = o;
        }
    }
}

extern "C" void kernel_launch(void* const* d_in, const int* in_sizes, int n_in,
                              void* d_out, int out_size) {
    const float* V     = (const float*)d_in[0];
    const float* h_t   = (const float*)d_in[1];
    const float* s_t   = (const float*)d_in[2];
    const float* W_v   = (const float*)d_in[3];
    const float* W_g   = (const float*)d_in[4];
    const float* W_s   = (const float*)d_in[5];
    const float* w_h   = (const float*)d_in[6];
    const float* w_h_s = (const float*)d_in[7];
    float* out = (float*)d_out;

    cudaFuncSetAttribute(k2, cudaFuncAttributeMaxDynamicSharedMemorySize, K2_SMEM);

    k1<<<256, 256>>>(h_t, s_t, W_v, W_g, W_s);
    k1b<<<256, 256>>>(w_h_s);
    k2<<<1024, 256, K2_SMEM>>>(V, h_t, s_t, w_h, out);
}

// round 17
// speedup vs baseline: 1.2839x; 1.0368x over previous
#include <cuda_runtime.h>
#include <cuda_bf16.h>
#include <cstdint>

#define BATCH 2048
#define LR 49          // K_REG
#define DIM 2048

// k2 SMEM: 2 stages of {A fp32 98x72 (28224B) + B bf16 64x72 (9216B)} + extras
#define ASTAGE   28224
#define STAGE    37440
#define OFF_EX   74880
#define K2_SMEM  76928

// __device__ scratch (allocation-free)
__device__ __nv_bfloat16 wv_bf[LR * DIM];        // bf16 copy of W_v
__device__ float part_scr[16 * BATCH * LR];      // [type*8+ksp][batch][k] partials
__device__ float g_scr[BATCH * LR];              // h_t @ W_g^T (reduced)
__device__ float sent_scr[BATCH];                // sentinel logit

__device__ __forceinline__ uint32_t smem_u32(const void* p) {
    uint32_t a;
    asm("{ .reg .u64 t; cvta.to.shared.u64 t, %1; cvt.u32.u64 %0, t; }" : "=r"(a) : "l"(p));
    return a;
}
__device__ __forceinline__ unsigned packbf(float x, float y) {
    __nv_bfloat162 t = __floats2bfloat162_rn(x, y);
    return *(unsigned*)&t;
}

// ---------------------------------------------------------------------------
// Kernel 1: split-K MMA GEMM (measured 12.7us). grid 256.
// ---------------------------------------------------------------------------
__global__ __launch_bounds__(256) void k1(
    const float* __restrict__ h_t, const float* __restrict__ s_t,
    const float* __restrict__ W_v, const float* __restrict__ W_g,
    const float* __restrict__ W_s)
{
    __shared__ __align__(16) unsigned char raw[29184];
    __nv_bfloat16* A_sm = (__nv_bfloat16*)raw;            // 128 x 72 bf16
    __nv_bfloat16* B_sm = (__nv_bfloat16*)(raw + 18432);  // 56 x 72 bf16
    unsigned* Au = (unsigned*)A_sm;
    unsigned* Bu = (unsigned*)B_sm;
    float (*P)[57] = (float (*)[57])raw;

    const int tid = threadIdx.x;
    const int warp = tid >> 5, lane = tid & 31;
    const int typ = blockIdx.x >> 7;
    const int btile = (blockIdx.x >> 3) & 15;
    const int ksp = blockIdx.x & 7;
    const int b0 = btile * 128;
    const int kbase = ksp * 256;
    const float* X = typ ? s_t : h_t;
    const float* W = typ ? W_s : W_g;
    float* dst = part_scr + (size_t)(typ * 8 + ksp) * BATCH * LR;

    if (tid < 98) {
        int i = blockIdx.x * 98 + tid;
        float4 v = ((const float4*)W_v)[i];
        __nv_bfloat162 lo = __floats2bfloat162_rn(v.x, v.y);
        __nv_bfloat162 hi = __floats2bfloat162_rn(v.z, v.w);
        __nv_bfloat162* d = (__nv_bfloat162*)(wv_bf) + (size_t)i * 2;
        d[0] = lo; d[1] = hi;
    }

    for (int i = tid; i < 29184 / 4; i += 256) ((unsigned*)raw)[i] = 0u;

    const float* asrc[8]; int adst[8];
    #pragma unroll
    for (int s = 0; s < 8; s++) {
        int a = s * 256 + tid;
        int row = a >> 4, c4 = a & 15;
        asrc[s] = X + (size_t)(b0 + row) * DIM + kbase + c4 * 4;
        adst[s] = row * 72 + c4 * 4;
    }
    const float* bsrc[4]; int bdst[4]; bool bact[4]; bool bzero[4];
    #pragma unroll
    for (int s = 0; s < 4; s++) {
        int idx = s * 256 + tid;
        bact[s] = (idx < 896);
        int row = idx >> 4, c4 = idx & 15;
        bzero[s] = (row >= LR);
        int rowc = (row < LR) ? row : 0;
        bsrc[s] = W + (size_t)rowc * DIM + kbase + c4 * 4;
        bdst[s] = row * 72 + c4 * 4;
    }

    float acc[7][4];
    #pragma unroll
    for (int j = 0; j < 7; j++) { acc[j][0]=acc[j][1]=acc[j][2]=acc[j][3]=0.f; }

    float4 ra[8], rbv[4];
    #pragma unroll
    for (int s = 0; s < 8; s++) ra[s] = *(const float4*)(asrc[s]);
    #pragma unroll
    for (int s = 0; s < 4; s++) if (bact[s]) rbv[s] = *(const float4*)(bsrc[s]);
    __syncthreads();

    #pragma unroll 1
    for (int ch = 0; ch < 4; ch++) {
        #pragma unroll
        for (int s = 0; s < 8; s++) {
            __nv_bfloat162 p0 = __floats2bfloat162_rn(ra[s].x, ra[s].y);
            __nv_bfloat162 p1 = __floats2bfloat162_rn(ra[s].z, ra[s].w);
            __nv_bfloat162* d = (__nv_bfloat162*)(A_sm + adst[s]);
            d[0] = p0; d[1] = p1;
        }
        #pragma unroll
        for (int s = 0; s < 4; s++) {
            if (bact[s]) {
                float4 v = bzero[s] ? make_float4(0.f,0.f,0.f,0.f) : rbv[s];
                __nv_bfloat162 p0 = __floats2bfloat162_rn(v.x, v.y);
                __nv_bfloat162 p1 = __floats2bfloat162_rn(v.z, v.w);
                __nv_bfloat162* d = (__nv_bfloat162*)(B_sm + bdst[s]);
                d[0] = p0; d[1] = p1;
            }
        }
        __syncthreads();
        if (ch + 1 < 4) {
            #pragma unroll
            for (int s = 0; s < 8; s++) ra[s] = *(const float4*)(asrc[s] + (ch + 1) * 64);
            #pragma unroll
            for (int s = 0; s < 4; s++) if (bact[s]) rbv[s] = *(const float4*)(bsrc[s] + (ch + 1) * 64);
        }
        #pragma unroll
        for (int st = 0; st < 4; st++) {
            int baseu = st * 8;
            int ai = (warp * 16 + (lane >> 2)) * 36 + baseu + (lane & 3);
            unsigned a0 = Au[ai];
            unsigned a1 = Au[ai + 8 * 36];
            unsigned a2 = Au[ai + 4];
            unsigned a3 = Au[ai + 8 * 36 + 4];
            #pragma unroll
            for (int j = 0; j < 7; j++) {
                int bidx = (j * 8 + (lane >> 2)) * 36 + baseu + (lane & 3);
                unsigned bb0 = Bu[bidx];
                unsigned bb1 = Bu[bidx + 4];
                asm volatile(
                    "mma.sync.aligned.m16n8k16.row.col.f32.bf16.bf16.f32 "
                    "{%0,%1,%2,%3}, {%4,%5,%6,%7}, {%8,%9}, {%0,%1,%2,%3};\n"
                    : "+f"(acc[j][0]), "+f"(acc[j][1]), "+f"(acc[j][2]), "+f"(acc[j][3])
                    : "r"(a0), "r"(a1), "r"(a2), "r"(a3), "r"(bb0), "r"(bb1));
            }
        }
        __syncthreads();
    }

    #pragma unroll
    for (int j = 0; j < 7; j++) {
        int r = warp * 16 + (lane >> 2);
        int c = j * 8 + 2 * (lane & 3);
        P[r][c]         = acc[j][0];
        P[r][c + 1]     = acc[j][1];
        P[r + 8][c]     = acc[j][2];
        P[r + 8][c + 1] = acc[j][3];
    }
    __syncthreads();
    for (int idx = tid; idx < 128 * LR; idx += 256) {
        int row = idx / LR, k = idx - row * LR;
        dst[(size_t)(b0 + row) * LR + k] = P[row][k];
    }
}

// ---------------------------------------------------------------------------
// Kernel 1b: reduce split-K partials -> g_scr; sent[b] (~3us)
// ---------------------------------------------------------------------------
__global__ __launch_bounds__(256) void k1b(const float* __restrict__ w_h_s)
{
    const int warp = threadIdx.x >> 5, lane = threadIdx.x & 31;
    const int b = blockIdx.x * 8 + warp;
    float s = 0.f;

    if (lane < LR) {
        float g = 0.f, S = 0.f;
        #pragma unroll
        for (int i = 0; i < 8; i++) {
            g += part_scr[((size_t)i * BATCH + b) * LR + lane];
            S += part_scr[((size_t)(8 + i) * BATCH + b) * LR + lane];
        }
        g_scr[(size_t)b * LR + lane] = g;
        s = tanhf(g + S) * w_h_s[lane];
    }
    if (lane + 32 < LR) {
        float g = 0.f, S = 0.f;
        #pragma unroll
        for (int i = 0; i < 8; i++) {
            g += part_scr[((size_t)i * BATCH + b) * LR + lane + 32];
            S += part_scr[((size_t)(8 + i) * BATCH + b) * LR + lane + 32];
        }
        g_scr[(size_t)b * LR + lane + 32] = g;
        s += tanhf(g + S) * w_h_s[lane + 32];
    }
    #pragma unroll
    for (int o = 16; o > 0; o >>= 1) s += __shfl_xor_sync(0xffffffffu, s, o);
    if (lane == 0) sent_scr[b] = s;
}

// ---------------------------------------------------------------------------
// Kernel 2: R12 structure with cp.async 2-stage pipeline. A lands as fp32 in
// SMEM (converted to bf16 in the fragment load); B bf16 via cp.async from
// wv_bf. Copies for chunk c+1 are in flight during ALL of chunk c.
// grid 1024 (2 batches/CTA), block 256, 76.9KB dyn smem -> 2 CTAs/SM.
// ---------------------------------------------------------------------------
__global__ __launch_bounds__(256) void k2(
    const float* __restrict__ V, const float* __restrict__ h_t,
    const float* __restrict__ s_t, const float* __restrict__ w_h,
    float* __restrict__ out)
{
    extern __shared__ __align__(16) unsigned char smraw[];

    const int tid = threadIdx.x;
    const int warp = tid >> 5, lane = tid & 31;
    const int b0 = blockIdx.x * 2, b1 = b0 + 1;

    float (*Wv)[65] = (float (*)[65])smraw;     // aliases stage0 after GEMM
    float* gk      = (float*)(smraw + OFF_EX);          // [128]
    float* wh      = (float*)(smraw + OFF_EX + 512);    // [64]
    float* zsm     = (float*)(smraw + OFF_EX + 768);    // [128]
    float* alpha_s = (float*)(smraw + OFF_EX + 1280);   // [128]
    float* bet     = (float*)(smraw + OFF_EX + 1792);   // [2]

    const uint32_t smbase = smem_u32(smraw);

    // zero B pad rows 49..63 in BOTH stages (cp.async never writes them)
    for (int i = tid; i < 540; i += 256) {
        ((unsigned*)(smraw + ASTAGE))[49 * 36 + i] = 0u;
        ((unsigned*)(smraw + STAGE + ASTAGE))[49 * 36 + i] = 0u;
    }

    const float* Vb0 = V + (size_t)b0 * LR * DIM;
    const float* Vb1 = V + (size_t)b1 * LR * DIM;

    // cp.async slot descriptors.
    // A: 1568 float4 granules/chunk (2 batches x 49 rows x 16), 7 slots
    const float* asrc[7]; uint32_t adst[7]; bool aact[7];
    #pragma unroll
    for (int s = 0; s < 7; s++) {
        int a = s * 256 + tid;
        aact[s] = (a < 1568);
        int batch = (a >= 784) ? 1 : 0;
        int idx = a - 784 * batch;
        int row = idx >> 4, c4 = idx & 15;
        if (!aact[s]) { row = 0; c4 = 0; }
        asrc[s] = (batch ? Vb1 : Vb0) + (size_t)row * DIM + c4 * 4;
        adst[s] = smbase + (uint32_t)(((batch * 49 + row) * 72 + c4 * 4) * 4);
    }
    // B: 392 16B granules/chunk (49 rows x 8), 2 slots
    const __nv_bfloat16* bsrc[2]; uint32_t bdst[2]; bool bact[2];
    #pragma unroll
    for (int s = 0; s < 2; s++) {
        int bidx = s * 256 + tid;
        bact[s] = (bidx < 392);
        int row = bidx >> 3, q = bidx & 7;
        if (!bact[s]) { row = 0; q = 0; }
        bsrc[s] = wv_bf + (size_t)row * DIM + q * 8;
        bdst[s] = smbase + ASTAGE + (uint32_t)((row * 72 + q * 8) * 2);
    }

    // fragment A rows (logical 0..127 -> packed smem rows, clamp >=49 dup)
    int fr = warp * 16 + (lane >> 2);
    int t0 = (fr < 64) ? fr : fr - 64;  if (t0 > 48) t0 = 48;
    const int a0l = ((fr < 64) ? 0 : 49) + t0;
    int fr8 = fr + 8;
    int t1 = (fr8 < 64) ? fr8 : fr8 - 64; if (t1 > 48) t1 = 48;
    const int a1l = ((fr8 < 64) ? 0 : 49) + t1;

    auto issue = [&](int ch) {
        const uint32_t soff = (uint32_t)((ch & 1) * STAGE);
        #pragma unroll
        for (int s = 0; s < 7; s++) {
            if (aact[s])
                asm volatile("cp.async.cg.shared.global [%0], [%1], 16;\n"
                             :: "r"(adst[s] + soff), "l"(asrc[s] + ch * 64) : "memory");
        }
        #pragma unroll
        for (int s = 0; s < 2; s++) {
            if (bact[s])
                asm volatile("cp.async.cg.shared.global [%0], [%1], 16;\n"
                             :: "r"(bdst[s] + soff), "l"(bsrc[s] + ch * 64) : "memory");
        }
        asm volatile("cp.async.commit_group;\n" ::: "memory");
    };

    float acc[8][4];
    #pragma unroll
    for (int j = 0; j < 8; j++) {
        #pragma unroll
        for (int c = 0; c < 4; c++) acc[j][c] = 0.f;
    }

    // prologue: stage 0 (chunk 0) + stage 1 (chunk 1)
    issue(0);
    issue(1);

    #pragma unroll 1
    for (int ch = 0; ch < 32; ch++) {
        const int cur = (ch & 1) * STAGE;
        asm volatile("cp.async.wait_group 1;\n" ::: "memory");
        __syncthreads();                       // stage cur ready (all threads)

        const float* Af = (const float*)(smraw + cur);
        const unsigned* Bu = (const unsigned*)(smraw + cur + ASTAGE);

        #pragma unroll
        for (int st = 0; st < 4; st++) {
            const int c1 = st * 16 + (lane & 3) * 2;
            float2 v00 = *(const float2*)(Af + a0l * 72 + c1);
            float2 v10 = *(const float2*)(Af + a1l * 72 + c1);
            float2 v01 = *(const float2*)(Af + a0l * 72 + c1 + 8);
            float2 v11 = *(const float2*)(Af + a1l * 72 + c1 + 8);
            unsigned a0 = packbf(v00.x, v00.y);
            unsigned a1 = packbf(v10.x, v10.y);
            unsigned a2 = packbf(v01.x, v01.y);
            unsigned a3 = packbf(v11.x, v11.y);
            int baseu = st * 8;
            #pragma unroll
            for (int j = 0; j < 8; j++) {
                int bidx = (j * 8 + (lane >> 2)) * 36 + baseu + (lane & 3);
                unsigned bb0 = Bu[bidx];
                unsigned bb1 = Bu[bidx + 4];
                asm volatile(
                    "mma.sync.aligned.m16n8k16.row.col.f32.bf16.bf16.f32 "
                    "{%0,%1,%2,%3}, {%4,%5,%6,%7}, {%8,%9}, {%0,%1,%2,%3};\n"
                    : "+f"(acc[j][0]), "+f"(acc[j][1]), "+f"(acc[j][2]), "+f"(acc[j][3])
                    : "r"(a0), "r"(a1), "r"(a2), "r"(a3), "r"(bb0), "r"(bb1));
            }
        }
        __syncthreads();                       // all reads of stage cur done

        if (ch + 2 < 32) issue(ch + 2);        // refill the freed stage
        else asm volatile("cp.async.commit_group;\n" ::: "memory");
    }

    // ---- epilogue: dump accumulators into aliased SMEM (stage0) ----
    #pragma unroll
    for (int j = 0; j < 8; j++) {
        int r = warp * 16 + (lane >> 2);
        int c = j * 8 + 2 * (lane & 3);
        Wv[r][c]         = acc[j][0];
        Wv[r][c + 1]     = acc[j][1];
        Wv[r + 8][c]     = acc[j][2];
        Wv[r + 8][c + 1] = acc[j][3];
    }
    if (tid < LR) {
        gk[tid]      = g_scr[(size_t)b0 * LR + tid];
        gk[64 + tid] = g_scr[(size_t)b1 * LR + tid];
        wh[tid]      = w_h[tid];
    }
    __syncthreads();

    // z_t[l] = sum_k tanh(WvV[l,k] + g[k]) * w_h[k]
    // (rows 49-63 / 113-127 are duplicates of row 48/112 -> finite, never read)
    {
        int lv = tid >> 1, q = tid & 1;    // lv 0..127
        int gb = lv & 64;
        float z = 0.f;
        for (int k = q; k < LR; k += 2)
            z += tanhf(Wv[lv][k] + gk[gb + k]) * wh[k];
        z += __shfl_xor_sync(0xffffffffu, z, 1);
        if (q == 0) zsm[lv] = z;
    }
    __syncthreads();

    // softmax over 50 logits, warps 0/1 (one per batch)
    if (warp < 2) {
        float v0 = (lane < LR) ? zsm[warp * 64 + lane] : -1e30f;
        float v1 = -1e30f;
        if (lane + 32 < LR)       v1 = zsm[warp * 64 + lane + 32];
        else if (lane + 32 == LR) v1 = sent_scr[b0 + warp];
        float m = fmaxf(v0, v1);
        #pragma unroll
        for (int o = 16; o > 0; o >>= 1) m = fmaxf(m, __shfl_xor_sync(0xffffffffu, m, o));
        float e0 = __expf(v0 - m), e1 = __expf(v1 - m);
        float s = e0 + e1;
        #pragma unroll
        for (int o = 16; o > 0; o >>= 1) s += __shfl_xor_sync(0xffffffffu, s, o);
        float inv = 1.f / s;
        if (lane < LR)       alpha_s[warp * 64 + lane]      = e0 * inv;
        if (lane + 32 < LR)  alpha_s[warp * 64 + lane + 32] = e1 * inv;
        if (lane == 17)      bet[warp] = e1 * inv;   // logit index 49
    }
    __syncthreads();

    // pass 2: c_t + output. Both d-halves of a batch fused -> 14 loads/unroll
    #pragma unroll 1
    for (int pbv = 0; pbv < 2; pbv++) {
        const float* Vb = pbv ? Vb1 : Vb0;
        const float* ap = alpha_s + pbv * 64;
        float c0x = 0.f, c0y = 0.f, c0z = 0.f, c0w = 0.f;
        float c1x = 0.f, c1y = 0.f, c1z = 0.f, c1w = 0.f;
        #pragma unroll 7
        for (int l = 0; l < LR; l++) {
            float a = ap[l];
            float4 v0 = *(const float4*)(Vb + (size_t)l * DIM + tid * 4);
            float4 v1 = *(const float4*)(Vb + (size_t)l * DIM + 1024 + tid * 4);
            c0x += a * v0.x; c0y += a * v0.y; c0z += a * v0.z; c0w += a * v0.w;
            c1x += a * v1.x; c1y += a * v1.y; c1z += a * v1.z; c1w += a * v1.w;
        }
        int b = pbv ? b1 : b0;
        float be = bet[pbv];
        float om = 1.f - be;
        {
            float4 s4 = *(const float4*)(s_t + (size_t)b * DIM + tid * 4);
            float4 h4 = *(const float4*)(h_t + (size_t)b * DIM + tid * 4);
            float4 o;
            o.x = be * s4.x + om * c0x + h4.x;
            o.y = be * s4.y + om * c0y + h4.y;
            o.z = be * s4.z + om * c0z + h4.z;
            o.w = be * s4.w + om * c0w + h4.w;
            *(float4*)(out + (size_t)b * DIM + tid * 4) = o;
        }
        {
            float4 s4 = *(const float4*)(s_t + (size_t)b * DIM + 1024 + tid * 4);
            float4 h4 = *(const float4*)(h_t + (size_t)b * DIM + 1024 + tid * 4);
            float4 o;
            o.x = be * s4.x + om * c1x + h4.x;
            o.y = be * s4.y + om * c1y + h4.y;
            o.z = be * s4.z + om * c1z + h4.z;
            o.w = be * s4.w + om * c1w + h4.w;
            *(float4*)(out + (size_t)b * DIM + 1024 + tid * 4) = o;
        }
    }
}

extern "C" void kernel_launch(void* const* d_in, const int* in_sizes, int n_in,
                              void* d_out, int out_size) {
    const float* V     = (const float*)d_in[0];
    const float* h_t   = (const float*)d_in[1];
    const float* s_t   = (const float*)d_in[2];
    const float* W_v   = (const float*)d_in[3];
    const float* W_g   = (const float*)d_in[4];
    const float* W_s   = (const float*)d_in[5];
    const float* w_h   = (const float*)d_in[6];
    const float* w_h_s = (const float*)d_in[7];
    float* out = (float*)d_out;

    cudaFuncSetAttribute(k2, cudaFuncAttributeMaxDynamicSharedMemorySize, K2_SMEM);

    k1<<<256, 256>>>(h_t, s_t, W_v, W_g, W_s);
    k1b<<<256, 256>>>(w_h_s);
    k2<<<1024, 256, K2_SMEM>>>(V, h_t, s_t, w_h, out);
}